// round 3
// baseline (speedup 1.0000x reference)
#include <cuda_runtime.h>
#include <cuda_bf16.h>

#define B_     16
#define N_     2048
#define NCTX   2047          // n_ctx = N - NQ
#define NSPLIT 16
#define OFFOUT (16LL*2048*64)

// scratch: per-batch partial Gram matrices C (96x32) per split, and P^T (32x64)
__device__ float g_C[B_ * NSPLIT * 96 * 32];
__device__ float g_P[B_ * 32 * 64];

// ---------------------------------------------------------------------------
// Kernel A: per (batch, split) partial C = X96[:, kv] @ Q_kv^T   (96 x 32)
//   rows 0..31 of X96 are Q, rows 32..95 are the categorical block.
// grid (NSPLIT, B), 256 threads. Each block handles 128 n-columns (4 tiles of 32).
// ---------------------------------------------------------------------------
__global__ void __launch_bounds__(256) kA(const float* __restrict__ x) {
    __shared__ float tile[96 * 33];   // padded rows (33) -> conflict-free
    const int s = blockIdx.x, b = blockIdx.y;
    const int tid = threadIdx.x;
    const int tj = tid & 31;          // output column j (q row)
    const int ti = tid >> 5;          // 0..7, owns 12 output rows
    const float* xb = x + (size_t)b * 160 * N_;

    float acc[12];
#pragma unroll
    for (int k = 0; k < 12; k++) acc[k] = 0.f;

    const int nbase = s * 128;
    for (int t = 0; t < 4; t++) {
        const int n0 = nbase + t * 32;
        __syncthreads();
        for (int idx = tid; idx < 96 * 32; idx += 256) {
            const int r = idx >> 5, cc = idx & 31;
            const int n = n0 + cc;
            tile[r * 33 + cc] = (n < NCTX) ? xb[r * N_ + n] : 0.f;
        }
        __syncthreads();
#pragma unroll 4
        for (int nn = 0; nn < 32; nn++) {
            const float qv = tile[tj * 33 + nn];
#pragma unroll
            for (int k = 0; k < 12; k++)
                acc[k] += tile[(ti * 12 + k) * 33 + nn] * qv;
        }
    }
    float* outp = g_C + (size_t)(b * NSPLIT + s) * 3072;
#pragma unroll
    for (int k = 0; k < 12; k++) outp[(ti * 12 + k) * 32 + tj] = acc[k];
}

// ---------------------------------------------------------------------------
// Kernel B: per batch, reduce partial C, then the closed-form 3-layer recursion
//   G = C[0:32]  (32x32),  T = C[32:96]  (64x32)
//   S0 = Emb @ T
//   for l: W = diag(alpha_l) S ; Wsum += W ; S += c * M @ (W @ G)
//   P^T[j][cc] = c * sum_d Emb[d][cc] * Wsum[d][j]
// grid B, 256 threads. Thread owns (row i = tid>>2, 8 cols j0 = (tid&3)*8).
// ---------------------------------------------------------------------------
__global__ void __launch_bounds__(256) kB(const float* __restrict__ alpha,
                                          const float* __restrict__ kpp,
                                          const float* __restrict__ emb,
                                          const float* __restrict__ M) {
    __shared__ float sC[3072];
    __shared__ float sS[2048];
    __shared__ float sW[64 * 33];     // padded: read strided by row
    __shared__ float sY[2048];
    __shared__ float sWs[2048];
    const int b = blockIdx.x, tid = threadIdx.x;

    for (int idx = tid; idx < 3072; idx += 256) {
        float v = 0.f;
        const float* p = g_C + (size_t)b * (NSPLIT * 3072) + idx;
#pragma unroll
        for (int sp = 0; sp < NSPLIT; sp++) v += p[sp * 3072];
        sC[idx] = v;
    }
    __syncthreads();

    const int i = tid >> 2;            // 0..63
    const int j0 = (tid & 3) * 8;      // 0,8,16,24
    float acc[8];

    // S0 = Emb @ T
#pragma unroll
    for (int u = 0; u < 8; u++) acc[u] = 0.f;
    for (int k = 0; k < 64; k++) {
        const float ev = emb[i * 64 + k];
        const float* row = &sC[(32 + k) * 32 + j0];
#pragma unroll
        for (int u = 0; u < 8; u++) acc[u] += ev * row[u];
    }
#pragma unroll
    for (int u = 0; u < 8; u++) { sS[i * 32 + j0 + u] = acc[u]; sWs[i * 32 + j0 + u] = 0.f; }
    __syncthreads();

    const float c = kpp[0] / (float)NCTX;

    for (int l = 0; l < 3; l++) {
        const float al = alpha[l * 64 + i];
#pragma unroll
        for (int u = 0; u < 8; u++) {
            const float w = al * sS[i * 32 + j0 + u];
            sW[i * 33 + j0 + u] = w;
            sWs[i * 32 + j0 + u] += w;
        }
        __syncthreads();
        // Y = W @ G   (G = sC rows 0..31)
#pragma unroll
        for (int u = 0; u < 8; u++) acc[u] = 0.f;
        for (int k = 0; k < 32; k++) {
            const float wv = sW[i * 33 + k];
            const float* g = &sC[k * 32 + j0];
#pragma unroll
            for (int u = 0; u < 8; u++) acc[u] += wv * g[u];
        }
#pragma unroll
        for (int u = 0; u < 8; u++) sY[i * 32 + j0 + u] = acc[u];
        __syncthreads();
        // S += c * M @ Y
#pragma unroll
        for (int u = 0; u < 8; u++) acc[u] = 0.f;
        for (int k = 0; k < 64; k++) {
            const float mv = M[i * 64 + k];
            const float* y = &sY[k * 32 + j0];
#pragma unroll
            for (int u = 0; u < 8; u++) acc[u] += mv * y[u];
        }
#pragma unroll
        for (int u = 0; u < 8; u++) sS[i * 32 + j0 + u] += c * acc[u];
        __syncthreads();
    }

    // P^T[j][cc] = c * Emb^T Wsum ; reuse i as cc (0..63)
    const int cc = i;
#pragma unroll
    for (int u = 0; u < 8; u++) acc[u] = 0.f;
    for (int d = 0; d < 64; d++) {
        const float ev = emb[d * 64 + cc];
        const float* wr = &sWs[d * 32 + j0];
#pragma unroll
        for (int u = 0; u < 8; u++) acc[u] += ev * wr[u];
    }
#pragma unroll
    for (int u = 0; u < 8; u++)
        g_P[(size_t)b * 2048 + (j0 + u) * 64 + cc] = c * acc[u];
}

// ---------------------------------------------------------------------------
// Kernel C: logits[b,n,c] = Emb^T f0_n + P q_n ; softmax -> predictions
// grid (N/128, B), 256 threads, dyn smem = 73728 B.
// Each warp owns 16 columns; processes 4 at a time (float4 smem loads),
// each lane computes c = lane and lane+32; softmax via warp shuffles.
// ---------------------------------------------------------------------------
__global__ void __launch_bounds__(256) kC(const float* __restrict__ x,
                                          const float* __restrict__ emb,
                                          float* __restrict__ out) {
    extern __shared__ float sm[];
    float* sEmb = sm;             // 4096
    float* sPt  = sm + 4096;      // 2048 (P^T: [j][c])
    float* sQ   = sm + 6144;      // 32*128
    float* sF   = sm + 10240;     // 64*128
    const int pb = blockIdx.x, b = blockIdx.y;
    const int tid = threadIdx.x, l = tid & 31, w = tid >> 5;
    const int n0 = pb * 128;
    const float* xb = x + (size_t)b * 160 * N_;

    for (int idx = tid; idx < 4096; idx += 256) sEmb[idx] = emb[idx];
    for (int idx = tid; idx < 2048; idx += 256) sPt[idx] = g_P[(size_t)b * 2048 + idx];
    for (int idx = tid; idx < 4096; idx += 256) {
        const int r = idx >> 7, ccx = idx & 127;
        sQ[idx] = xb[r * N_ + n0 + ccx];
    }
    for (int idx = tid; idx < 8192; idx += 256) {
        const int r = idx >> 7, ccx = idx & 127;
        sF[idx] = xb[(96 + r) * N_ + n0 + ccx];
    }
    __syncthreads();

    for (int p = 0; p < 4; p++) {
        const int c0 = w * 16 + p * 4;
        float a0[4], a1[4];
#pragma unroll
        for (int u = 0; u < 4; u++) { a0[u] = 0.f; a1[u] = 0.f; }
#pragma unroll 4
        for (int d = 0; d < 64; d++) {
            const float e0 = sEmb[d * 64 + l];
            const float e1 = sEmb[d * 64 + l + 32];
            const float4 fv = *reinterpret_cast<const float4*>(&sF[d * 128 + c0]);
            a0[0] += e0 * fv.x; a1[0] += e1 * fv.x;
            a0[1] += e0 * fv.y; a1[1] += e1 * fv.y;
            a0[2] += e0 * fv.z; a1[2] += e1 * fv.z;
            a0[3] += e0 * fv.w; a1[3] += e1 * fv.w;
        }
#pragma unroll 4
        for (int j = 0; j < 32; j++) {
            const float p0 = sPt[j * 64 + l];
            const float p1 = sPt[j * 64 + l + 32];
            const float4 qv = *reinterpret_cast<const float4*>(&sQ[j * 128 + c0]);
            a0[0] += p0 * qv.x; a1[0] += p1 * qv.x;
            a0[1] += p0 * qv.y; a1[1] += p1 * qv.y;
            a0[2] += p0 * qv.z; a1[2] += p1 * qv.z;
            a0[3] += p0 * qv.w; a1[3] += p1 * qv.w;
        }
#pragma unroll
        for (int u = 0; u < 4; u++) {
            float m = fmaxf(a0[u], a1[u]);
#pragma unroll
            for (int o = 16; o > 0; o >>= 1) m = fmaxf(m, __shfl_xor_sync(0xffffffffu, m, o));
            const float e0 = __expf(a0[u] - m);
            const float e1 = __expf(a1[u] - m);
            float su = e0 + e1;
#pragma unroll
            for (int o = 16; o > 0; o >>= 1) su += __shfl_xor_sync(0xffffffffu, su, o);
            const float inv = 1.f / su;
            const size_t base = ((size_t)b * N_ + n0 + c0 + u) * 64;
            out[base + l]            = a0[u];
            out[base + l + 32]       = a1[u];
            out[OFFOUT + base + l]      = e0 * inv;
            out[OFFOUT + base + l + 32] = e1 * inv;
        }
    }
}

extern "C" void kernel_launch(void* const* d_in, const int* in_sizes, int n_in,
                              void* d_out, int out_size) {
    const float* x     = (const float*)d_in[0];
    const float* alpha = (const float*)d_in[1];
    const float* kp    = (const float*)d_in[2];
    const float* emb   = (const float*)d_in[3];
    const float* M     = (const float*)d_in[4];
    float* out = (float*)d_out;

    cudaFuncSetAttribute(kC, cudaFuncAttributeMaxDynamicSharedMemorySize, 18432 * 4);

    kA<<<dim3(NSPLIT, B_), 256>>>(x);
    kB<<<B_, 256>>>(alpha, kp, emb, M);
    kC<<<dim3(N_ / 128, B_), 256, 18432 * 4>>>(x, emb, out);
}